// round 14
// baseline (speedup 1.0000x reference)
#include <cuda_runtime.h>
#include <cuda_fp8.h>
#include <cstdint>

// ============================================================================
// Linear8bit on plain sm_103 (no 'a' target -> no tcgen05). Legacy FP8 QMMA:
//   mma.sync.aligned.m16n8k32.row.col.f32.e4m3.e4m3.f32
//
// R14: mainloop pinned at tensor=67% across all structural variants (R8-R13)
// -> treat as ISA-rate plateau. Recover the remaining overhead instead:
// PERSISTENT CTAs (296 = occ2 x 148SM) with a flat global k-counter so the
// 3-stage cp.async pipeline streams ACROSS tile boundaries (next tile's
// stages prefetched during current tile's last kiters + epilogue).
// Compute/sync path identical to R13 (warp 32x64, kk stagger, occ 2).
// Pack: 512-thr blocks, 8 int4/thread.
// ============================================================================

namespace l8 {

constexpr int Bn = 4, Mdim = 2048, Kdim = 4096, Ndim = 4096;
constexpr int ROWS = Bn * Mdim;          // 8192
constexpr int BM = 128, BN = 128, BK = 128;
constexpr int KITERS = Kdim / BK;        // 32
constexpr int STAGES = 3;
constexpr int NTHREADS = 256;
constexpr int NTILES = (ROWS / BM) * (Ndim / BN);  // 2048
constexpr int GRID = 296;                // 148 SMs x occ 2

constexpr int A_BYTES = BM * BK;         // 16 KB
constexpr int B_BYTES = BN * BK;         // 16 KB
constexpr int STAGE_BYTES = A_BYTES + B_BYTES;          // 32 KB
constexpr int SMEM_TOTAL = STAGES * STAGE_BYTES;        // 96 KB

__device__ uint8_t g_xq8[(size_t)ROWS * Kdim];   // 33.5 MB (e4m3)
__device__ uint8_t g_w8[(size_t)Ndim * Kdim];    // 16.8 MB (e4m3)

// ---- fused pack: int32 -> e4m3, one launch, 8 int4/thread, 512 thr ----
constexpr int XQ_N4 = ROWS * Kdim / 4;
constexpr int W_N4  = Ndim * Kdim / 4;
constexpr int PACK_PER_THREAD = 8;
constexpr int PACK_TOTAL = XQ_N4 + W_N4;          // 12.58M (div by 4096)
constexpr int PACK_BLOCKS = PACK_TOTAL / (PACK_PER_THREAD * 512);

__device__ __forceinline__ uchar4 cvt4(int4 v) {
  uchar4 o;
  o.x = (uint8_t)__nv_cvt_float_to_fp8((float)v.x, __NV_SATFINITE, __NV_E4M3);
  o.y = (uint8_t)__nv_cvt_float_to_fp8((float)v.y, __NV_SATFINITE, __NV_E4M3);
  o.z = (uint8_t)__nv_cvt_float_to_fp8((float)v.z, __NV_SATFINITE, __NV_E4M3);
  o.w = (uint8_t)__nv_cvt_float_to_fp8((float)v.w, __NV_SATFINITE, __NV_E4M3);
  return o;
}

__global__ void __launch_bounds__(512)
pack_fp8_fused(const int4* __restrict__ xq, const int4* __restrict__ w) {
  int i0 = (blockIdx.x * 512 + threadIdx.x) * PACK_PER_THREAD;
  int4 v[PACK_PER_THREAD];
  const int4* src;
  uchar4* dst;
  int base;
  if (i0 < XQ_N4) {
    src = xq; dst = (uchar4*)g_xq8; base = i0;
  } else {
    src = w; dst = (uchar4*)g_w8; base = i0 - XQ_N4;
  }
#pragma unroll
  for (int j = 0; j < PACK_PER_THREAD; ++j) v[j] = src[base + j];
#pragma unroll
  for (int j = 0; j < PACK_PER_THREAD; ++j) dst[base + j] = cvt4(v[j]);
}

__device__ __forceinline__ uint32_t smem_u32(const void* p) {
  uint32_t a;
  asm("{ .reg .u64 t; cvta.to.shared.u64 t, %1; cvt.u32.u64 %0, t; }"
      : "=r"(a) : "l"(p));
  return a;
}
__device__ __forceinline__ uint32_t sw128(uint32_t o) {
  return o ^ ((o >> 3) & 0x70);
}
__device__ __forceinline__ void cp16(uint32_t s, const void* g) {
  asm volatile("cp.async.cg.shared.global [%0], [%1], 16;"
               :: "r"(s), "l"(g) : "memory");
}
__device__ __forceinline__ void cp_commit() {
  asm volatile("cp.async.commit_group;" ::: "memory");
}
__device__ __forceinline__ void cp_wait1() {
  asm volatile("cp.async.wait_group 1;" ::: "memory");
}
__device__ __forceinline__ void ldm_x4(uint32_t* r, uint32_t addr) {
  asm volatile(
      "ldmatrix.sync.aligned.m8n8.x4.shared.b16 {%0,%1,%2,%3}, [%4];"
      : "=r"(r[0]), "=r"(r[1]), "=r"(r[2]), "=r"(r[3]) : "r"(addr));
}
__device__ __forceinline__ void mma_e4m3(float* d, const uint32_t* a,
                                         uint32_t b0, uint32_t b1) {
  asm volatile(
      "mma.sync.aligned.m16n8k32.row.col.f32.e4m3.e4m3.f32 "
      "{%0,%1,%2,%3}, {%4,%5,%6,%7}, {%8,%9}, {%0,%1,%2,%3};"
      : "+f"(d[0]), "+f"(d[1]), "+f"(d[2]), "+f"(d[3])
      : "r"(a[0]), "r"(a[1]), "r"(a[2]), "r"(a[3]), "r"(b0), "r"(b1));
}

__global__ void __launch_bounds__(NTHREADS, 2)
linear8_kernel(const float* __restrict__ sx, const float* __restrict__ ws,
               const float* __restrict__ bias, float* __restrict__ out) {
  extern __shared__ char smem[];
  uint32_t smem_base = smem_u32(smem);
  const int tid = threadIdx.x;
  const int lane = tid & 31;
  const int wid = tid >> 5;
  const int wr = wid >> 1;            // warp row 0..3 -> 32 M rows each
  const int wc = wid & 1;             // warp col 0..1 -> 64 N cols each
  const int kkoff = (wid >> 2) << 1;  // anti-phase same-SMSP warp pairs

  const int bid = blockIdx.x;
  // number of tiles this CTA owns: tiles bid, bid+GRID, ...
  const int my_ntiles = (NTILES - bid + GRID - 1) / GRID;
  const int ktotal = my_ntiles * KITERS;

  // issue one pipeline-stage load for flat k-index kgl
  auto load_for = [&](int kgl) {
    const int tile = bid + (kgl >> 5) * GRID;
    const int mt = tile & (ROWS / BM - 1);
    const int nt = tile >> 6;
    const int kin = kgl & (KITERS - 1);
    const uint8_t* ag = g_xq8 + (size_t)mt * BM * Kdim + (size_t)kin * BK;
    const uint8_t* bg = g_w8 + (size_t)nt * BN * Kdim + (size_t)kin * BK;
    const int s = kgl % STAGES;
    const uint32_t as = smem_base + s * STAGE_BYTES;
    const uint32_t bs = as + A_BYTES;
#pragma unroll
    for (int i = 0; i < 4; ++i) {
      int idx = tid + i * NTHREADS;
      int row = idx >> 3, c = idx & 7;
      cp16(as + sw128((uint32_t)(row * BK + c * 16)),
           ag + (size_t)row * Kdim + c * 16);
    }
#pragma unroll
    for (int i = 0; i < 4; ++i) {
      int idx = tid + i * NTHREADS;
      int row = idx >> 3, c = idx & 7;
      cp16(bs + sw128((uint32_t)(row * BK + c * 16)),
           bg + (size_t)row * Kdim + c * 16);
    }
    cp_commit();
  };

  const int lrow = lane & 15;
  const int lc = lane >> 4;
  const int arow0 = wr * 32 + lrow;
  const int arow1 = arow0 + 16;
  const int brow0 = wc * 64 + lrow;

  float acc[2][8][4];
#pragma unroll
  for (int mi = 0; mi < 2; ++mi)
#pragma unroll
    for (int ni = 0; ni < 8; ++ni)
#pragma unroll
      for (int j = 0; j < 4; ++j) acc[mi][ni][j] = 0.f;

  // ---- prologue: first two stages of first tile ----
  load_for(0);
  load_for(1);

  for (int kg = 0; kg < ktotal; ++kg) {
    const int s = kg % STAGES;
    cp_wait1();
    __syncthreads();

    if (kg + 2 < ktotal) {
      load_for(kg + 2);  // may belong to the NEXT tile: pipeline streams on
    } else {
      cp_commit();       // empty group keeps wait_group accounting uniform
    }

    const uint32_t a_st = smem_base + s * STAGE_BYTES;
    const uint32_t b_st = a_st + A_BYTES;

#pragma unroll
    for (int kk0 = 0; kk0 < 4; ++kk0) {
      const int kk = (kk0 + kkoff) & 3;
      uint32_t afr[2][4], bfr[4][4];
      {
        uint32_t ch = (uint32_t)(kk * 2 + lc);
        ldm_x4(afr[0], a_st + (uint32_t)(arow0 * BK) +
                           ((ch ^ (uint32_t)(arow0 & 7)) << 4));
        ldm_x4(afr[1], a_st + (uint32_t)(arow1 * BK) +
                           ((ch ^ (uint32_t)(arow1 & 7)) << 4));
#pragma unroll
        for (int p = 0; p < 4; ++p) {
          int brow = brow0 + p * 16;
          ldm_x4(bfr[p], b_st + (uint32_t)(brow * BK) +
                             ((ch ^ (uint32_t)(brow & 7)) << 4));
        }
      }
#pragma unroll
      for (int mi = 0; mi < 2; ++mi)
#pragma unroll
        for (int p = 0; p < 4; ++p) {
          mma_e4m3(acc[mi][2 * p + 0], afr[mi], bfr[p][0], bfr[p][2]);
          mma_e4m3(acc[mi][2 * p + 1], afr[mi], bfr[p][1], bfr[p][3]);
        }
    }

    // ---- tile finished: epilogue (registers + global only; no smem) ----
    if ((kg & (KITERS - 1)) == (KITERS - 1)) {
      const int tile = bid + (kg >> 5) * GRID;
      const int mtile = tile & (ROWS / BM - 1);
      const int ntile = tile >> 6;
      const int qrow = lane >> 2;
      const int qcol = (lane & 3) * 2;
      const int gcol_base = ntile * BN + wc * 64 + qcol;
      const int grow_base = mtile * BM + wr * 32 + qrow;
#pragma unroll
      for (int mi = 0; mi < 2; ++mi) {
        const int r0 = grow_base + mi * 16;
        const int r1 = r0 + 8;
        const float sx0 = __ldg(sx + r0);
        const float sx1 = __ldg(sx + r1);
        float* o0 = out + (size_t)r0 * Ndim + gcol_base;
        float* o1 = out + (size_t)r1 * Ndim + gcol_base;
#pragma unroll
        for (int ni = 0; ni < 8; ++ni) {
          const int c = gcol_base + ni * 8;
          const float2 w2 = __ldg((const float2*)(ws + c));
          const float2 b2 = __ldg((const float2*)(bias + c));
          float2 v0, v1;
          v0.x = acc[mi][ni][0] * (sx0 * w2.x) + b2.x;
          v0.y = acc[mi][ni][1] * (sx0 * w2.y) + b2.y;
          v1.x = acc[mi][ni][2] * (sx1 * w2.x) + b2.x;
          v1.y = acc[mi][ni][3] * (sx1 * w2.y) + b2.y;
          *(float2*)(o0 + ni * 8) = v0;
          *(float2*)(o1 + ni * 8) = v1;
        }
      }
#pragma unroll
      for (int mi = 0; mi < 2; ++mi)
#pragma unroll
        for (int ni = 0; ni < 8; ++ni)
#pragma unroll
          for (int j = 0; j < 4; ++j) acc[mi][ni][j] = 0.f;
    }
  }
}

}  // namespace l8

extern "C" void kernel_launch(void* const* d_in, const int* in_sizes, int n_in,
                              void* d_out, int out_size) {
  (void)in_sizes; (void)n_in; (void)out_size;
  const int*   xq_i32 = (const int*)d_in[0];
  const float* sx     = (const float*)d_in[1];
  const int*   w_i32  = (const int*)d_in[2];
  const float* ws     = (const float*)d_in[3];
  const float* bia    = (const float*)d_in[4];
  float* out = (float*)d_out;

  l8::pack_fp8_fused<<<l8::PACK_BLOCKS, 512>>>((const int4*)xq_i32,
                                               (const int4*)w_i32);

  cudaFuncSetAttribute(l8::linear8_kernel,
                       cudaFuncAttributeMaxDynamicSharedMemorySize,
                       l8::SMEM_TOTAL);
  l8::linear8_kernel<<<l8::GRID, l8::NTHREADS, l8::SMEM_TOTAL>>>(
      sx, ws, bia, out);
}

// round 15
// speedup vs baseline: 1.0975x; 1.0975x over previous
#include <cuda_runtime.h>
#include <cuda_fp8.h>
#include <cstdint>

// ============================================================================
// Linear8bit on plain sm_103 (no 'a' target -> no tcgen05). Legacy FP8 QMMA:
//   mma.sync.aligned.m16n8k32.row.col.f32.e4m3.e4m3.f32
//
// R15 = R13 (best: 712.9us; GEMM 677, tensor 67%) with modulo-free stage
// bookkeeping. Plateau evidence: tensor pinned at 67% across 6 structural
// variants (sync x3, occupancy x3, reg pressure, issue order, stagger);
// every deviation from this shape regressed. Warp tile 32x64 maximizes
// MMA:LDSM ratio within the 128-reg budget.
// ============================================================================

namespace l8 {

constexpr int Bn = 4, Mdim = 2048, Kdim = 4096, Ndim = 4096;
constexpr int ROWS = Bn * Mdim;          // 8192
constexpr int BM = 128, BN = 128, BK = 128;
constexpr int KITERS = Kdim / BK;        // 32
constexpr int STAGES = 3;
constexpr int NTHREADS = 256;

constexpr int A_BYTES = BM * BK;         // 16 KB
constexpr int B_BYTES = BN * BK;         // 16 KB
constexpr int STAGE_BYTES = A_BYTES + B_BYTES;          // 32 KB
constexpr int SMEM_TOTAL = STAGES * STAGE_BYTES;        // 96 KB

__device__ uint8_t g_xq8[(size_t)ROWS * Kdim];   // 33.5 MB (e4m3)
__device__ uint8_t g_w8[(size_t)Ndim * Kdim];    // 16.8 MB (e4m3)

// ---- fused pack: int32 -> e4m3, both tensors in one launch, 4 int4/thread --
constexpr int XQ_N4 = ROWS * Kdim / 4;
constexpr int W_N4  = Ndim * Kdim / 4;
constexpr int PACK_PER_THREAD = 4;
constexpr int PACK_TOTAL = XQ_N4 + W_N4;
constexpr int PACK_BLOCKS = (PACK_TOTAL / PACK_PER_THREAD + 255) / 256;

__device__ __forceinline__ uchar4 cvt4(int4 v) {
  uchar4 o;
  o.x = (uint8_t)__nv_cvt_float_to_fp8((float)v.x, __NV_SATFINITE, __NV_E4M3);
  o.y = (uint8_t)__nv_cvt_float_to_fp8((float)v.y, __NV_SATFINITE, __NV_E4M3);
  o.z = (uint8_t)__nv_cvt_float_to_fp8((float)v.z, __NV_SATFINITE, __NV_E4M3);
  o.w = (uint8_t)__nv_cvt_float_to_fp8((float)v.w, __NV_SATFINITE, __NV_E4M3);
  return o;
}

__global__ void pack_fp8_fused(const int4* __restrict__ xq,
                               const int4* __restrict__ w) {
  int i0 = (blockIdx.x * blockDim.x + threadIdx.x) * PACK_PER_THREAD;
  int4 v[PACK_PER_THREAD];
  const int4* src;
  uchar4* dst;
  int base;
  if (i0 < XQ_N4) {
    src = xq; dst = (uchar4*)g_xq8; base = i0;
  } else {
    src = w; dst = (uchar4*)g_w8; base = i0 - XQ_N4;
  }
#pragma unroll
  for (int j = 0; j < PACK_PER_THREAD; ++j) v[j] = src[base + j];
#pragma unroll
  for (int j = 0; j < PACK_PER_THREAD; ++j) dst[base + j] = cvt4(v[j]);
}

__device__ __forceinline__ uint32_t smem_u32(const void* p) {
  uint32_t a;
  asm("{ .reg .u64 t; cvta.to.shared.u64 t, %1; cvt.u32.u64 %0, t; }"
      : "=r"(a) : "l"(p));
  return a;
}
__device__ __forceinline__ uint32_t sw128(uint32_t o) {
  return o ^ ((o >> 3) & 0x70);
}
__device__ __forceinline__ void cp16(uint32_t s, const void* g) {
  asm volatile("cp.async.cg.shared.global [%0], [%1], 16;"
               :: "r"(s), "l"(g) : "memory");
}
__device__ __forceinline__ void cp_commit() {
  asm volatile("cp.async.commit_group;" ::: "memory");
}
__device__ __forceinline__ void cp_wait1() {
  asm volatile("cp.async.wait_group 1;" ::: "memory");
}
__device__ __forceinline__ void ldm_x4(uint32_t* r, uint32_t addr) {
  asm volatile(
      "ldmatrix.sync.aligned.m8n8.x4.shared.b16 {%0,%1,%2,%3}, [%4];"
      : "=r"(r[0]), "=r"(r[1]), "=r"(r[2]), "=r"(r[3]) : "r"(addr));
}
__device__ __forceinline__ void mma_e4m3(float* d, const uint32_t* a,
                                         uint32_t b0, uint32_t b1) {
  asm volatile(
      "mma.sync.aligned.m16n8k32.row.col.f32.e4m3.e4m3.f32 "
      "{%0,%1,%2,%3}, {%4,%5,%6,%7}, {%8,%9}, {%0,%1,%2,%3};"
      : "+f"(d[0]), "+f"(d[1]), "+f"(d[2]), "+f"(d[3])
      : "r"(a[0]), "r"(a[1]), "r"(a[2]), "r"(a[3]), "r"(b0), "r"(b1));
}

// cooperative cp.async of one stage (A 16KB + B 16KB), one commit group
__device__ __forceinline__ void load_stage(uint32_t stage_base, int kiter,
                                           const uint8_t* a_base,
                                           const uint8_t* b_base, int tid) {
  const uint8_t* ag = a_base + (size_t)kiter * BK;
  const uint8_t* bg = b_base + (size_t)kiter * BK;
  uint32_t as = stage_base;
  uint32_t bs = stage_base + A_BYTES;
#pragma unroll
  for (int i = 0; i < (BM * BK / 16) / NTHREADS; ++i) {  // 4
    int idx = tid + i * NTHREADS;
    int row = idx >> 3, c = idx & 7;
    cp16(as + sw128((uint32_t)(row * BK + c * 16)),
         ag + (size_t)row * Kdim + c * 16);
  }
#pragma unroll
  for (int i = 0; i < (BN * BK / 16) / NTHREADS; ++i) {  // 4
    int idx = tid + i * NTHREADS;
    int row = idx >> 3, c = idx & 7;
    cp16(bs + sw128((uint32_t)(row * BK + c * 16)),
         bg + (size_t)row * Kdim + c * 16);
  }
  cp_commit();
}

__global__ void __launch_bounds__(NTHREADS, 2)
linear8_kernel(const float* __restrict__ sx, const float* __restrict__ ws,
               const float* __restrict__ bias, float* __restrict__ out) {
  extern __shared__ char smem[];
  uint32_t smem_base = smem_u32(smem);
  const int tid = threadIdx.x;
  const int lane = tid & 31;
  const int wid = tid >> 5;
  const int wr = wid >> 1;            // warp row 0..3 -> 32 M rows each
  const int wc = wid & 1;             // warp col 0..1 -> 64 N cols each
  const int kkoff = (wid >> 2) << 1;  // anti-phase same-SMSP warp pairs

  const int mtile = blockIdx.x & (ROWS / BM - 1);  // 64 (fast-varying)
  const int ntile = blockIdx.x >> 6;               // 32

  const uint8_t* a_base = g_xq8 + (size_t)mtile * BM * Kdim;
  const uint8_t* b_base = g_w8 + (size_t)ntile * BN * Kdim;

  const int lrow = lane & 15;
  const int lc = lane >> 4;         // 16-byte chunk within 32B k-step

  float acc[2][8][4];
#pragma unroll
  for (int mi = 0; mi < 2; ++mi)
#pragma unroll
    for (int ni = 0; ni < 8; ++ni)
#pragma unroll
      for (int j = 0; j < 4; ++j) acc[mi][ni][j] = 0.f;

  // ---- pipeline prologue ----
  load_stage(smem_base, 0, a_base, b_base, tid);
  load_stage(smem_base + STAGE_BYTES, 1, a_base, b_base, tid);

  // addr(row, kk, lc) = stage + row*128 + ((kk*2 + lc) ^ (row & 7)) * 16
  const int arow0 = wr * 32 + lrow;
  const int arow1 = arow0 + 16;
  const int brow0 = wc * 64 + lrow;   // n-pair p covers +p*16

  // rotating stage bases (modulo-free)
  uint32_t cm_st = smem_base;                    // compute stage
  uint32_t ld_st = smem_base + 2 * STAGE_BYTES;  // next load stage
  const uint32_t wrap = smem_base + STAGES * STAGE_BYTES;

  for (int k = 0; k < KITERS; ++k) {
    cp_wait1();
    __syncthreads();

    const int kn = k + STAGES - 1;
    if (kn < KITERS) {
      load_stage(ld_st, kn, a_base, b_base, tid);
      ld_st += STAGE_BYTES;
      if (ld_st == wrap) ld_st = smem_base;
    } else {
      cp_commit();  // empty group keeps wait_group accounting uniform
    }

    const uint32_t a_st = cm_st;
    const uint32_t b_st = cm_st + A_BYTES;

#pragma unroll
    for (int kk0 = 0; kk0 < 4; ++kk0) {
      const int kk = (kk0 + kkoff) & 3;  // anti-phase same-SMSP warp pairs
      uint32_t afr[2][4], bfr[4][4];
      {
        uint32_t ch = (uint32_t)(kk * 2 + lc);
        ldm_x4(afr[0], a_st + (uint32_t)(arow0 * BK) +
                           ((ch ^ (uint32_t)(arow0 & 7)) << 4));
        ldm_x4(afr[1], a_st + (uint32_t)(arow1 * BK) +
                           ((ch ^ (uint32_t)(arow1 & 7)) << 4));
#pragma unroll
        for (int p = 0; p < 4; ++p) {
          int brow = brow0 + p * 16;
          ldm_x4(bfr[p], b_st + (uint32_t)(brow * BK) +
                             ((ch ^ (uint32_t)(brow & 7)) << 4));
        }
      }
      // bfr[p]: r0 = b0 of n-tile 2p, r1 = b0 of n-tile 2p+1,
      //         r2 = b1 of n-tile 2p, r3 = b1 of n-tile 2p+1
#pragma unroll
      for (int mi = 0; mi < 2; ++mi)
#pragma unroll
        for (int p = 0; p < 4; ++p) {
          mma_e4m3(acc[mi][2 * p + 0], afr[mi], bfr[p][0], bfr[p][2]);
          mma_e4m3(acc[mi][2 * p + 1], afr[mi], bfr[p][1], bfr[p][3]);
        }
    }

    cm_st += STAGE_BYTES;
    if (cm_st == wrap) cm_st = smem_base;
  }

  // ---- epilogue: fused dequant + bias, float2 stores ----
  const int qrow = lane >> 2;            // 0..7
  const int qcol = (lane & 3) * 2;       // 0,2,4,6
  const int gcol_base = ntile * BN + wc * 64 + qcol;
  const int grow_base = mtile * BM + wr * 32 + qrow;

#pragma unroll
  for (int mi = 0; mi < 2; ++mi) {
    const int r0 = grow_base + mi * 16;
    const int r1 = r0 + 8;
    const float sx0 = __ldg(sx + r0);
    const float sx1 = __ldg(sx + r1);
    float* o0 = out + (size_t)r0 * Ndim + gcol_base;
    float* o1 = out + (size_t)r1 * Ndim + gcol_base;
#pragma unroll
    for (int ni = 0; ni < 8; ++ni) {
      const int c = gcol_base + ni * 8;
      const float2 w2 = __ldg((const float2*)(ws + c));
      const float2 b2 = __ldg((const float2*)(bias + c));
      float2 v0, v1;
      v0.x = acc[mi][ni][0] * (sx0 * w2.x) + b2.x;
      v0.y = acc[mi][ni][1] * (sx0 * w2.y) + b2.y;
      v1.x = acc[mi][ni][2] * (sx1 * w2.x) + b2.x;
      v1.y = acc[mi][ni][3] * (sx1 * w2.y) + b2.y;
      *(float2*)(o0 + ni * 8) = v0;
      *(float2*)(o1 + ni * 8) = v1;
    }
  }
}

}  // namespace l8

extern "C" void kernel_launch(void* const* d_in, const int* in_sizes, int n_in,
                              void* d_out, int out_size) {
  (void)in_sizes; (void)n_in; (void)out_size;
  const int*   xq_i32 = (const int*)d_in[0];
  const float* sx     = (const float*)d_in[1];
  const int*   w_i32  = (const int*)d_in[2];
  const float* ws     = (const float*)d_in[3];
  const float* bia    = (const float*)d_in[4];
  float* out = (float*)d_out;

  l8::pack_fp8_fused<<<l8::PACK_BLOCKS, 256>>>((const int4*)xq_i32,
                                               (const int4*)w_i32);

  cudaFuncSetAttribute(l8::linear8_kernel,
                       cudaFuncAttributeMaxDynamicSharedMemorySize,
                       l8::SMEM_TOTAL);
  dim3 grid((l8::ROWS / l8::BM) * (l8::Ndim / l8::BN));  // 2048
  l8::linear8_kernel<<<grid, l8::NTHREADS, l8::SMEM_TOTAL>>>(
      sx, ws, bia, out);
}

// round 16
// speedup vs baseline: 1.1534x; 1.0510x over previous
#include <cuda_runtime.h>
#include <cuda_fp8.h>
#include <cstdint>

// ============================================================================
// Linear8bit on plain sm_103 (no 'a' target -> no tcgen05). Legacy FP8 QMMA:
//   mma.sync.aligned.m16n8k32.row.col.f32.e4m3.e4m3.f32
//
// R13 = R8 (best: 678us GEMM, tensor 67%) + kk phase stagger: same-SMSP warp
// pairs (wid, wid+4) execute identical code and are phase-locked by the
// per-kiter __syncthreads -> their LDSM bursts align and the tensor pipe
// idles. Warps 4-7 rotate the kk order by 2 so one warp MMAs while its
// SMSP partner does LDSM. kk order only permutes exact integer fp32 adds.
// ============================================================================

namespace l8 {

constexpr int Bn = 4, Mdim = 2048, Kdim = 4096, Ndim = 4096;
constexpr int ROWS = Bn * Mdim;          // 8192
constexpr int BM = 128, BN = 128, BK = 128;
constexpr int KITERS = Kdim / BK;        // 32
constexpr int STAGES = 3;
constexpr int NTHREADS = 256;

constexpr int A_BYTES = BM * BK;         // 16 KB
constexpr int B_BYTES = BN * BK;         // 16 KB
constexpr int STAGE_BYTES = A_BYTES + B_BYTES;          // 32 KB
constexpr int SMEM_TOTAL = STAGES * STAGE_BYTES;        // 96 KB

__device__ uint8_t g_xq8[(size_t)ROWS * Kdim];   // 33.5 MB (e4m3)
__device__ uint8_t g_w8[(size_t)Ndim * Kdim];    // 16.8 MB (e4m3)

// ---- fused pack: int32 -> e4m3, both tensors in one launch, 4 int4/thread --
constexpr int XQ_N4 = ROWS * Kdim / 4;
constexpr int W_N4  = Ndim * Kdim / 4;
constexpr int PACK_PER_THREAD = 4;
constexpr int PACK_TOTAL = XQ_N4 + W_N4;
constexpr int PACK_BLOCKS = (PACK_TOTAL / PACK_PER_THREAD + 255) / 256;

__device__ __forceinline__ uchar4 cvt4(int4 v) {
  uchar4 o;
  o.x = (uint8_t)__nv_cvt_float_to_fp8((float)v.x, __NV_SATFINITE, __NV_E4M3);
  o.y = (uint8_t)__nv_cvt_float_to_fp8((float)v.y, __NV_SATFINITE, __NV_E4M3);
  o.z = (uint8_t)__nv_cvt_float_to_fp8((float)v.z, __NV_SATFINITE, __NV_E4M3);
  o.w = (uint8_t)__nv_cvt_float_to_fp8((float)v.w, __NV_SATFINITE, __NV_E4M3);
  return o;
}

__global__ void pack_fp8_fused(const int4* __restrict__ xq,
                               const int4* __restrict__ w) {
  int i0 = (blockIdx.x * blockDim.x + threadIdx.x) * PACK_PER_THREAD;
  int4 v[PACK_PER_THREAD];
  const int4* src;
  uchar4* dst;
  int base;
  if (i0 < XQ_N4) {
    src = xq; dst = (uchar4*)g_xq8; base = i0;
  } else {
    src = w; dst = (uchar4*)g_w8; base = i0 - XQ_N4;
  }
#pragma unroll
  for (int j = 0; j < PACK_PER_THREAD; ++j) v[j] = src[base + j];
#pragma unroll
  for (int j = 0; j < PACK_PER_THREAD; ++j) dst[base + j] = cvt4(v[j]);
}

__device__ __forceinline__ uint32_t smem_u32(const void* p) {
  uint32_t a;
  asm("{ .reg .u64 t; cvta.to.shared.u64 t, %1; cvt.u32.u64 %0, t; }"
      : "=r"(a) : "l"(p));
  return a;
}
__device__ __forceinline__ uint32_t sw128(uint32_t o) {
  return o ^ ((o >> 3) & 0x70);
}
__device__ __forceinline__ void cp16(uint32_t s, const void* g) {
  asm volatile("cp.async.cg.shared.global [%0], [%1], 16;"
               :: "r"(s), "l"(g) : "memory");
}
__device__ __forceinline__ void cp_commit() {
  asm volatile("cp.async.commit_group;" ::: "memory");
}
__device__ __forceinline__ void cp_wait1() {
  asm volatile("cp.async.wait_group 1;" ::: "memory");
}
__device__ __forceinline__ void ldm_x4(uint32_t* r, uint32_t addr) {
  asm volatile(
      "ldmatrix.sync.aligned.m8n8.x4.shared.b16 {%0,%1,%2,%3}, [%4];"
      : "=r"(r[0]), "=r"(r[1]), "=r"(r[2]), "=r"(r[3]) : "r"(addr));
}
__device__ __forceinline__ void mma_e4m3(float* d, const uint32_t* a,
                                         uint32_t b0, uint32_t b1) {
  asm volatile(
      "mma.sync.aligned.m16n8k32.row.col.f32.e4m3.e4m3.f32 "
      "{%0,%1,%2,%3}, {%4,%5,%6,%7}, {%8,%9}, {%0,%1,%2,%3};"
      : "+f"(d[0]), "+f"(d[1]), "+f"(d[2]), "+f"(d[3])
      : "r"(a[0]), "r"(a[1]), "r"(a[2]), "r"(a[3]), "r"(b0), "r"(b1));
}

// cooperative cp.async of one stage (A 16KB + B 16KB), one commit group
__device__ __forceinline__ void load_stage(uint32_t smem_base, int s, int kiter,
                                           const uint8_t* a_base,
                                           const uint8_t* b_base, int tid) {
  const uint8_t* ag = a_base + (size_t)kiter * BK;
  const uint8_t* bg = b_base + (size_t)kiter * BK;
  uint32_t as = smem_base + s * STAGE_BYTES;
  uint32_t bs = as + A_BYTES;
#pragma unroll
  for (int i = 0; i < (BM * BK / 16) / NTHREADS; ++i) {  // 4
    int idx = tid + i * NTHREADS;
    int row = idx >> 3, c = idx & 7;
    cp16(as + sw128((uint32_t)(row * BK + c * 16)),
         ag + (size_t)row * Kdim + c * 16);
  }
#pragma unroll
  for (int i = 0; i < (BN * BK / 16) / NTHREADS; ++i) {  // 4
    int idx = tid + i * NTHREADS;
    int row = idx >> 3, c = idx & 7;
    cp16(bs + sw128((uint32_t)(row * BK + c * 16)),
         bg + (size_t)row * Kdim + c * 16);
  }
  cp_commit();
}

__global__ void __launch_bounds__(NTHREADS, 2)
linear8_kernel(const float* __restrict__ sx, const float* __restrict__ ws,
               const float* __restrict__ bias, float* __restrict__ out) {
  extern __shared__ char smem[];
  uint32_t smem_base = smem_u32(smem);
  const int tid = threadIdx.x;
  const int lane = tid & 31;
  const int wid = tid >> 5;
  const int wr = wid >> 1;          // warp row 0..3 -> 32 M rows each
  const int wc = wid & 1;           // warp col 0..1 -> 64 N cols each
  const int kkoff = (wid >> 2) << 1;  // 0 for warps 0-3, 2 for warps 4-7

  const int mtile = blockIdx.x & (ROWS / BM - 1);  // 64 (fast-varying)
  const int ntile = blockIdx.x >> 6;               // 32

  const uint8_t* a_base = g_xq8 + (size_t)mtile * BM * Kdim;
  const uint8_t* b_base = g_w8 + (size_t)ntile * BN * Kdim;

  const int lrow = lane & 15;
  const int lc = lane >> 4;         // 16-byte chunk within 32B k-step

  float acc[2][8][4];
#pragma unroll
  for (int mi = 0; mi < 2; ++mi)
#pragma unroll
    for (int ni = 0; ni < 8; ++ni)
#pragma unroll
      for (int j = 0; j < 4; ++j) acc[mi][ni][j] = 0.f;

  // ---- pipeline prologue ----
#pragma unroll
  for (int s = 0; s < STAGES - 1; ++s)
    load_stage(smem_base, s, s, a_base, b_base, tid);

  // addr(row, kk, lc) = stage + row*128 + ((kk*2 + lc) ^ (row & 7)) * 16
  const int arow0 = wr * 32 + lrow;
  const int arow1 = arow0 + 16;
  const int brow0 = wc * 64 + lrow;   // n-pair p covers +p*16

  for (int k = 0; k < KITERS; ++k) {
    const int s = k % STAGES;
    cp_wait1();
    __syncthreads();

    const int kn = k + STAGES - 1;
    if (kn < KITERS) {
      load_stage(smem_base, kn % STAGES, kn, a_base, b_base, tid);
    } else {
      cp_commit();  // empty group keeps wait_group accounting uniform
    }

    const uint32_t a_st = smem_base + s * STAGE_BYTES;
    const uint32_t b_st = a_st + A_BYTES;

#pragma unroll
    for (int kk0 = 0; kk0 < 4; ++kk0) {
      const int kk = (kk0 + kkoff) & 3;  // anti-phase same-SMSP warp pairs
      uint32_t afr[2][4], bfr[4][4];
      {
        uint32_t ch = (uint32_t)(kk * 2 + lc);
        ldm_x4(afr[0], a_st + (uint32_t)(arow0 * BK) +
                           ((ch ^ (uint32_t)(arow0 & 7)) << 4));
        ldm_x4(afr[1], a_st + (uint32_t)(arow1 * BK) +
                           ((ch ^ (uint32_t)(arow1 & 7)) << 4));
#pragma unroll
        for (int p = 0; p < 4; ++p) {
          int brow = brow0 + p * 16;
          ldm_x4(bfr[p], b_st + (uint32_t)(brow * BK) +
                             ((ch ^ (uint32_t)(brow & 7)) << 4));
        }
      }
      // bfr[p]: r0 = b0 of n-tile 2p, r1 = b0 of n-tile 2p+1,
      //         r2 = b1 of n-tile 2p, r3 = b1 of n-tile 2p+1
#pragma unroll
      for (int mi = 0; mi < 2; ++mi)
#pragma unroll
        for (int p = 0; p < 4; ++p) {
          mma_e4m3(acc[mi][2 * p + 0], afr[mi], bfr[p][0], bfr[p][2]);
          mma_e4m3(acc[mi][2 * p + 1], afr[mi], bfr[p][1], bfr[p][3]);
        }
    }
  }

  // ---- epilogue: fused dequant + bias, float2 stores ----
  const int qrow = lane >> 2;            // 0..7
  const int qcol = (lane & 3) * 2;       // 0,2,4,6
  const int gcol_base = ntile * BN + wc * 64 + qcol;
  const int grow_base = mtile * BM + wr * 32 + qrow;

#pragma unroll
  for (int mi = 0; mi < 2; ++mi) {
    const int r0 = grow_base + mi * 16;
    const int r1 = r0 + 8;
    const float sx0 = __ldg(sx + r0);
    const float sx1 = __ldg(sx + r1);
    float* o0 = out + (size_t)r0 * Ndim + gcol_base;
    float* o1 = out + (size_t)r1 * Ndim + gcol_base;
#pragma unroll
    for (int ni = 0; ni < 8; ++ni) {
      const int c = gcol_base + ni * 8;
      const float2 w2 = __ldg((const float2*)(ws + c));
      const float2 b2 = __ldg((const float2*)(bias + c));
      float2 v0, v1;
      v0.x = acc[mi][ni][0] * (sx0 * w2.x) + b2.x;
      v0.y = acc[mi][ni][1] * (sx0 * w2.y) + b2.y;
      v1.x = acc[mi][ni][2] * (sx1 * w2.x) + b2.x;
      v1.y = acc[mi][ni][3] * (sx1 * w2.y) + b2.y;
      *(float2*)(o0 + ni * 8) = v0;
      *(float2*)(o1 + ni * 8) = v1;
    }
  }
}

}  // namespace l8

extern "C" void kernel_launch(void* const* d_in, const int* in_sizes, int n_in,
                              void* d_out, int out_size) {
  (void)in_sizes; (void)n_in; (void)out_size;
  const int*   xq_i32 = (const int*)d_in[0];
  const float* sx     = (const float*)d_in[1];
  const int*   w_i32  = (const int*)d_in[2];
  const float* ws     = (const float*)d_in[3];
  const float* bia    = (const float*)d_in[4];
  float* out = (float*)d_out;

  l8::pack_fp8_fused<<<l8::PACK_BLOCKS, 256>>>((const int4*)xq_i32,
                                               (const int4*)w_i32);

  cudaFuncSetAttribute(l8::linear8_kernel,
                       cudaFuncAttributeMaxDynamicSharedMemorySize,
                       l8::SMEM_TOTAL);
  dim3 grid((l8::ROWS / l8::BM) * (l8::Ndim / l8::BN));  // 2048
  l8::linear8_kernel<<<grid, l8::NTHREADS, l8::SMEM_TOTAL>>>(
      sx, ws, bia, out);
}

// round 17
// speedup vs baseline: 1.1535x; 1.0000x over previous
#include <cuda_runtime.h>
#include <cuda_fp8.h>
#include <cstdint>

// ============================================================================
// Linear8bit on plain sm_103 (no 'a' target -> no tcgen05). Legacy FP8 QMMA:
//   mma.sync.aligned.m16n8k32.row.col.f32.e4m3.e4m3.f32
//
// R13 = R8 (best: 678us GEMM, tensor 67%) + kk phase stagger: same-SMSP warp
// pairs (wid, wid+4) execute identical code and are phase-locked by the
// per-kiter __syncthreads -> their LDSM bursts align and the tensor pipe
// idles. Warps 4-7 rotate the kk order by 2 so one warp MMAs while its
// SMSP partner does LDSM. kk order only permutes exact integer fp32 adds.
// ============================================================================

namespace l8 {

constexpr int Bn = 4, Mdim = 2048, Kdim = 4096, Ndim = 4096;
constexpr int ROWS = Bn * Mdim;          // 8192
constexpr int BM = 128, BN = 128, BK = 128;
constexpr int KITERS = Kdim / BK;        // 32
constexpr int STAGES = 3;
constexpr int NTHREADS = 256;

constexpr int A_BYTES = BM * BK;         // 16 KB
constexpr int B_BYTES = BN * BK;         // 16 KB
constexpr int STAGE_BYTES = A_BYTES + B_BYTES;          // 32 KB
constexpr int SMEM_TOTAL = STAGES * STAGE_BYTES;        // 96 KB

__device__ uint8_t g_xq8[(size_t)ROWS * Kdim];   // 33.5 MB (e4m3)
__device__ uint8_t g_w8[(size_t)Ndim * Kdim];    // 16.8 MB (e4m3)

// ---- fused pack: int32 -> e4m3, both tensors in one launch, 4 int4/thread --
constexpr int XQ_N4 = ROWS * Kdim / 4;
constexpr int W_N4  = Ndim * Kdim / 4;
constexpr int PACK_PER_THREAD = 4;
constexpr int PACK_TOTAL = XQ_N4 + W_N4;
constexpr int PACK_BLOCKS = (PACK_TOTAL / PACK_PER_THREAD + 255) / 256;

__device__ __forceinline__ uchar4 cvt4(int4 v) {
  uchar4 o;
  o.x = (uint8_t)__nv_cvt_float_to_fp8((float)v.x, __NV_SATFINITE, __NV_E4M3);
  o.y = (uint8_t)__nv_cvt_float_to_fp8((float)v.y, __NV_SATFINITE, __NV_E4M3);
  o.z = (uint8_t)__nv_cvt_float_to_fp8((float)v.z, __NV_SATFINITE, __NV_E4M3);
  o.w = (uint8_t)__nv_cvt_float_to_fp8((float)v.w, __NV_SATFINITE, __NV_E4M3);
  return o;
}

__global__ void pack_fp8_fused(const int4* __restrict__ xq,
                               const int4* __restrict__ w) {
  int i0 = (blockIdx.x * blockDim.x + threadIdx.x) * PACK_PER_THREAD;
  int4 v[PACK_PER_THREAD];
  const int4* src;
  uchar4* dst;
  int base;
  if (i0 < XQ_N4) {
    src = xq; dst = (uchar4*)g_xq8; base = i0;
  } else {
    src = w; dst = (uchar4*)g_w8; base = i0 - XQ_N4;
  }
#pragma unroll
  for (int j = 0; j < PACK_PER_THREAD; ++j) v[j] = src[base + j];
#pragma unroll
  for (int j = 0; j < PACK_PER_THREAD; ++j) dst[base + j] = cvt4(v[j]);
}

__device__ __forceinline__ uint32_t smem_u32(const void* p) {
  uint32_t a;
  asm("{ .reg .u64 t; cvta.to.shared.u64 t, %1; cvt.u32.u64 %0, t; }"
      : "=r"(a) : "l"(p));
  return a;
}
__device__ __forceinline__ uint32_t sw128(uint32_t o) {
  return o ^ ((o >> 3) & 0x70);
}
__device__ __forceinline__ void cp16(uint32_t s, const void* g) {
  asm volatile("cp.async.cg.shared.global [%0], [%1], 16;"
               :: "r"(s), "l"(g) : "memory");
}
__device__ __forceinline__ void cp_commit() {
  asm volatile("cp.async.commit_group;" ::: "memory");
}
__device__ __forceinline__ void cp_wait1() {
  asm volatile("cp.async.wait_group 1;" ::: "memory");
}
__device__ __forceinline__ void ldm_x4(uint32_t* r, uint32_t addr) {
  asm volatile(
      "ldmatrix.sync.aligned.m8n8.x4.shared.b16 {%0,%1,%2,%3}, [%4];"
      : "=r"(r[0]), "=r"(r[1]), "=r"(r[2]), "=r"(r[3]) : "r"(addr));
}
__device__ __forceinline__ void mma_e4m3(float* d, const uint32_t* a,
                                         uint32_t b0, uint32_t b1) {
  asm volatile(
      "mma.sync.aligned.m16n8k32.row.col.f32.e4m3.e4m3.f32 "
      "{%0,%1,%2,%3}, {%4,%5,%6,%7}, {%8,%9}, {%0,%1,%2,%3};"
      : "+f"(d[0]), "+f"(d[1]), "+f"(d[2]), "+f"(d[3])
      : "r"(a[0]), "r"(a[1]), "r"(a[2]), "r"(a[3]), "r"(b0), "r"(b1));
}

// cooperative cp.async of one stage (A 16KB + B 16KB), one commit group
__device__ __forceinline__ void load_stage(uint32_t smem_base, int s, int kiter,
                                           const uint8_t* a_base,
                                           const uint8_t* b_base, int tid) {
  const uint8_t* ag = a_base + (size_t)kiter * BK;
  const uint8_t* bg = b_base + (size_t)kiter * BK;
  uint32_t as = smem_base + s * STAGE_BYTES;
  uint32_t bs = as + A_BYTES;
#pragma unroll
  for (int i = 0; i < (BM * BK / 16) / NTHREADS; ++i) {  // 4
    int idx = tid + i * NTHREADS;
    int row = idx >> 3, c = idx & 7;
    cp16(as + sw128((uint32_t)(row * BK + c * 16)),
         ag + (size_t)row * Kdim + c * 16);
  }
#pragma unroll
  for (int i = 0; i < (BN * BK / 16) / NTHREADS; ++i) {  // 4
    int idx = tid + i * NTHREADS;
    int row = idx >> 3, c = idx & 7;
    cp16(bs + sw128((uint32_t)(row * BK + c * 16)),
         bg + (size_t)row * Kdim + c * 16);
  }
  cp_commit();
}

__global__ void __launch_bounds__(NTHREADS, 2)
linear8_kernel(const float* __restrict__ sx, const float* __restrict__ ws,
               const float* __restrict__ bias, float* __restrict__ out) {
  extern __shared__ char smem[];
  uint32_t smem_base = smem_u32(smem);
  const int tid = threadIdx.x;
  const int lane = tid & 31;
  const int wid = tid >> 5;
  const int wr = wid >> 1;          // warp row 0..3 -> 32 M rows each
  const int wc = wid & 1;           // warp col 0..1 -> 64 N cols each
  const int kkoff = (wid >> 2) << 1;  // 0 for warps 0-3, 2 for warps 4-7

  const int mtile = blockIdx.x & (ROWS / BM - 1);  // 64 (fast-varying)
  const int ntile = blockIdx.x >> 6;               // 32

  const uint8_t* a_base = g_xq8 + (size_t)mtile * BM * Kdim;
  const uint8_t* b_base = g_w8 + (size_t)ntile * BN * Kdim;

  const int lrow = lane & 15;
  const int lc = lane >> 4;         // 16-byte chunk within 32B k-step

  float acc[2][8][4];
#pragma unroll
  for (int mi = 0; mi < 2; ++mi)
#pragma unroll
    for (int ni = 0; ni < 8; ++ni)
#pragma unroll
      for (int j = 0; j < 4; ++j) acc[mi][ni][j] = 0.f;

  // ---- pipeline prologue ----
#pragma unroll
  for (int s = 0; s < STAGES - 1; ++s)
    load_stage(smem_base, s, s, a_base, b_base, tid);

  // addr(row, kk, lc) = stage + row*128 + ((kk*2 + lc) ^ (row & 7)) * 16
  const int arow0 = wr * 32 + lrow;
  const int arow1 = arow0 + 16;
  const int brow0 = wc * 64 + lrow;   // n-pair p covers +p*16

  for (int k = 0; k < KITERS; ++k) {
    const int s = k % STAGES;
    cp_wait1();
    __syncthreads();

    const int kn = k + STAGES - 1;
    if (kn < KITERS) {
      load_stage(smem_base, kn % STAGES, kn, a_base, b_base, tid);
    } else {
      cp_commit();  // empty group keeps wait_group accounting uniform
    }

    const uint32_t a_st = smem_base + s * STAGE_BYTES;
    const uint32_t b_st = a_st + A_BYTES;

#pragma unroll
    for (int kk0 = 0; kk0 < 4; ++kk0) {
      const int kk = (kk0 + kkoff) & 3;  // anti-phase same-SMSP warp pairs
      uint32_t afr[2][4], bfr[4][4];
      {
        uint32_t ch = (uint32_t)(kk * 2 + lc);
        ldm_x4(afr[0], a_st + (uint32_t)(arow0 * BK) +
                           ((ch ^ (uint32_t)(arow0 & 7)) << 4));
        ldm_x4(afr[1], a_st + (uint32_t)(arow1 * BK) +
                           ((ch ^ (uint32_t)(arow1 & 7)) << 4));
#pragma unroll
        for (int p = 0; p < 4; ++p) {
          int brow = brow0 + p * 16;
          ldm_x4(bfr[p], b_st + (uint32_t)(brow * BK) +
                             ((ch ^ (uint32_t)(brow & 7)) << 4));
        }
      }
      // bfr[p]: r0 = b0 of n-tile 2p, r1 = b0 of n-tile 2p+1,
      //         r2 = b1 of n-tile 2p, r3 = b1 of n-tile 2p+1
#pragma unroll
      for (int mi = 0; mi < 2; ++mi)
#pragma unroll
        for (int p = 0; p < 4; ++p) {
          mma_e4m3(acc[mi][2 * p + 0], afr[mi], bfr[p][0], bfr[p][2]);
          mma_e4m3(acc[mi][2 * p + 1], afr[mi], bfr[p][1], bfr[p][3]);
        }
    }
  }

  // ---- epilogue: fused dequant + bias, float2 stores ----
  const int qrow = lane >> 2;            // 0..7
  const int qcol = (lane & 3) * 2;       // 0,2,4,6
  const int gcol_base = ntile * BN + wc * 64 + qcol;
  const int grow_base = mtile * BM + wr * 32 + qrow;

#pragma unroll
  for (int mi = 0; mi < 2; ++mi) {
    const int r0 = grow_base + mi * 16;
    const int r1 = r0 + 8;
    const float sx0 = __ldg(sx + r0);
    const float sx1 = __ldg(sx + r1);
    float* o0 = out + (size_t)r0 * Ndim + gcol_base;
    float* o1 = out + (size_t)r1 * Ndim + gcol_base;
#pragma unroll
    for (int ni = 0; ni < 8; ++ni) {
      const int c = gcol_base + ni * 8;
      const float2 w2 = __ldg((const float2*)(ws + c));
      const float2 b2 = __ldg((const float2*)(bias + c));
      float2 v0, v1;
      v0.x = acc[mi][ni][0] * (sx0 * w2.x) + b2.x;
      v0.y = acc[mi][ni][1] * (sx0 * w2.y) + b2.y;
      v1.x = acc[mi][ni][2] * (sx1 * w2.x) + b2.x;
      v1.y = acc[mi][ni][3] * (sx1 * w2.y) + b2.y;
      *(float2*)(o0 + ni * 8) = v0;
      *(float2*)(o1 + ni * 8) = v1;
    }
  }
}

}  // namespace l8

extern "C" void kernel_launch(void* const* d_in, const int* in_sizes, int n_in,
                              void* d_out, int out_size) {
  (void)in_sizes; (void)n_in; (void)out_size;
  const int*   xq_i32 = (const int*)d_in[0];
  const float* sx     = (const float*)d_in[1];
  const int*   w_i32  = (const int*)d_in[2];
  const float* ws     = (const float*)d_in[3];
  const float* bia    = (const float*)d_in[4];
  float* out = (float*)d_out;

  l8::pack_fp8_fused<<<l8::PACK_BLOCKS, 256>>>((const int4*)xq_i32,
                                               (const int4*)w_i32);

  cudaFuncSetAttribute(l8::linear8_kernel,
                       cudaFuncAttributeMaxDynamicSharedMemorySize,
                       l8::SMEM_TOTAL);
  dim3 grid((l8::ROWS / l8::BM) * (l8::Ndim / l8::BN));  // 2048
  l8::linear8_kernel<<<grid, l8::NTHREADS, l8::SMEM_TOTAL>>>(
      sx, ws, bia, out);
}